// round 1
// baseline (speedup 1.0000x reference)
#include <cuda_runtime.h>

// LightGCN: 3-layer propagation over COO adjacency, running-sum / 4.
// Strategy: counting-sort edges to CSR each launch (deterministic work),
// then 3x atomic-free warp-per-row gather SpMM, accumulating into d_out.

#define N_USERS 60000
#define N_ITEMS 40000
#define NN      100000          // N_NODES
#define NNZ_E   2000000
#define EMB     64
#define NV      (NN * EMB)      // 6.4M floats

// ---- scratch (device globals; no runtime allocation allowed) ----
__device__ float g_buf0[NV];
__device__ float g_buf1[NV];
__device__ int   g_count[NN];
__device__ int   g_start[NN];
__device__ int   g_cursor[NN];
__device__ int2  g_edge[NNZ_E];   // {col, bitcast(val)} sorted by row

#define SCAN_B 1024
#define NSCAN ((NN + SCAN_B - 1) / SCAN_B)   // 98 blocks
__device__ int g_part[NSCAN];

// ---- init: buf0 = concat(user_emb, item_emb); acc(d_out) = same ----
__global__ void k_init(const float4* __restrict__ u,
                       const float4* __restrict__ it,
                       float4* __restrict__ acc) {
    int i = blockIdx.x * blockDim.x + threadIdx.x;
    const int nU = N_USERS * EMB / 4;
    const int nT = NV / 4;
    if (i >= nT) return;
    float4 v = (i < nU) ? u[i] : it[i - nU];
    ((float4*)g_buf0)[i] = v;
    acc[i] = v;
}

__global__ void k_zero() {
    int i = blockIdx.x * blockDim.x + threadIdx.x;
    if (i < NN) g_count[i] = 0;
}

__global__ void k_hist(const int* __restrict__ rows) {
    int e = blockIdx.x * blockDim.x + threadIdx.x;
    if (e < NNZ_E) atomicAdd(&g_count[rows[e]], 1);
}

// block sums of 1024-element chunks
__global__ void k_scanA() {
    __shared__ int sh[256];
    int base = blockIdx.x * SCAN_B;
    int s = 0;
    for (int j = threadIdx.x; j < SCAN_B; j += 256) {
        int idx = base + j;
        if (idx < NN) s += g_count[idx];
    }
    sh[threadIdx.x] = s;
    __syncthreads();
    for (int off = 128; off > 0; off >>= 1) {
        if (threadIdx.x < off) sh[threadIdx.x] += sh[threadIdx.x + off];
        __syncthreads();
    }
    if (threadIdx.x == 0) g_part[blockIdx.x] = sh[0];
}

// exclusive scan of 98 partials (trivial serial)
__global__ void k_scanB() {
    if (threadIdx.x == 0) {
        int a = 0;
        for (int b = 0; b < NSCAN; b++) { int t = g_part[b]; g_part[b] = a; a += t; }
    }
}

// per-chunk exclusive scan + partial offset -> row_start, row_cursor
__global__ void k_scanC() {
    __shared__ int sh[SCAN_B];
    int i = blockIdx.x * SCAN_B + threadIdx.x;
    int v = (i < NN) ? g_count[i] : 0;
    sh[threadIdx.x] = v;
    __syncthreads();
    for (int off = 1; off < SCAN_B; off <<= 1) {
        int t = (threadIdx.x >= (unsigned)off) ? sh[threadIdx.x - off] : 0;
        __syncthreads();
        sh[threadIdx.x] += t;
        __syncthreads();
    }
    if (i < NN) {
        int excl = sh[threadIdx.x] - v + g_part[blockIdx.x];
        g_start[i]  = excl;
        g_cursor[i] = excl;
    }
}

__global__ void k_scatter(const float* __restrict__ vals,
                          const int* __restrict__ rows,
                          const int* __restrict__ cols) {
    int e = blockIdx.x * blockDim.x + threadIdx.x;
    if (e >= NNZ_E) return;
    int r = rows[e];
    int p = atomicAdd(&g_cursor[r], 1);
    g_edge[p] = make_int2(cols[e], __float_as_int(vals[e]));
}

// one warp per row; lane owns emb[2*lane .. 2*lane+1] (float2).
// phase 0: buf0 -> buf1;  phase 1: buf1 -> buf0.  acc += y always.
__global__ void k_spmm(int phase, float* __restrict__ acc) {
    int w    = (blockIdx.x * blockDim.x + threadIdx.x) >> 5;
    int lane = threadIdx.x & 31;
    if (w >= NN) return;
    const float2* __restrict__ x2 = (const float2*)(phase ? g_buf1 : g_buf0);
    float2*       __restrict__ o2 = (float2*)      (phase ? g_buf0 : g_buf1);

    int s = g_start[w];
    int n = g_count[w];
    float ax = 0.f, ay = 0.f;
    int j = 0;
    for (; j + 2 <= n; j += 2) {
        int2 e0 = g_edge[s + j];
        int2 e1 = g_edge[s + j + 1];
        float2 x0 = x2[e0.x * 32 + lane];
        float2 x1 = x2[e1.x * 32 + lane];
        float v0 = __int_as_float(e0.y);
        float v1 = __int_as_float(e1.y);
        ax = fmaf(v0, x0.x, ax); ay = fmaf(v0, x0.y, ay);
        ax = fmaf(v1, x1.x, ax); ay = fmaf(v1, x1.y, ay);
    }
    if (j < n) {
        int2 e0 = g_edge[s + j];
        float2 x0 = x2[e0.x * 32 + lane];
        float v0 = __int_as_float(e0.y);
        ax = fmaf(v0, x0.x, ax); ay = fmaf(v0, x0.y, ay);
    }
    int oi = w * 32 + lane;
    o2[oi] = make_float2(ax, ay);
    float2* a2 = (float2*)acc;
    float2 a = a2[oi];
    a2[oi] = make_float2(a.x + ax, a.y + ay);
}

__global__ void k_scale(float4* __restrict__ out) {
    int i = blockIdx.x * blockDim.x + threadIdx.x;
    if (i >= NV / 4) return;
    float4 v = out[i];
    v.x *= 0.25f; v.y *= 0.25f; v.z *= 0.25f; v.w *= 0.25f;
    out[i] = v;
}

extern "C" void kernel_launch(void* const* d_in, const int* in_sizes, int n_in,
                              void* d_out, int out_size) {
    const float4* u    = (const float4*)d_in[0];   // user_emb  [60000,64] f32
    const float4* it   = (const float4*)d_in[1];   // item_emb  [40000,64] f32
    const float*  vals = (const float*) d_in[2];   // adj_vals  [2M] f32
    const int*    rows = (const int*)   d_in[3];   // adj_rows  [2M] i32
    const int*    cols = (const int*)   d_in[4];   // adj_cols  [2M] i32
    float* out = (float*)d_out;                    // [100000, 64] f32

    k_init<<<(NV / 4 + 255) / 256, 256>>>(u, it, (float4*)out);
    k_zero<<<(NN + 255) / 256, 256>>>();
    k_hist<<<(NNZ_E + 255) / 256, 256>>>(rows);
    k_scanA<<<NSCAN, 256>>>();
    k_scanB<<<1, 32>>>();
    k_scanC<<<NSCAN, SCAN_B>>>();
    k_scatter<<<(NNZ_E + 255) / 256, 256>>>(vals, rows, cols);

    const int spmm_blocks = (NN * 32 + 255) / 256;   // one warp per row
    k_spmm<<<spmm_blocks, 256>>>(0, out);  // layer 1: buf0 -> buf1
    k_spmm<<<spmm_blocks, 256>>>(1, out);  // layer 2: buf1 -> buf0
    k_spmm<<<spmm_blocks, 256>>>(0, out);  // layer 3: buf0 -> buf1

    k_scale<<<(NV / 4 + 255) / 256, 256>>>((float4*)out);
}

// round 2
// speedup vs baseline: 1.3976x; 1.3976x over previous
#include <cuda_runtime.h>

// LightGCN: counting-sort COO -> CSR once per launch, then 3 atomic-free
// warp-per-row gather SpMM layers (float4 lanes, 2 edges per warp), and a
// single final combine pass out = 0.25*(ego0 + l1 + l2 + l3).

#define N_USERS 60000
#define N_ITEMS 40000
#define NN      100000          // N_NODES
#define NNZ_E   2000000
#define EMB     64
#define NV      (NN * EMB)      // 6.4M floats

// ---- scratch (device globals; no runtime allocation allowed) ----
__device__ float g_buf0[NV];      // layer-1 output
__device__ float g_buf1[NV];      // layer-2 output
__device__ float g_buf2[NV];      // layer-3 output
__device__ int   g_count[NN];
__device__ int   g_start[NN];
__device__ int   g_cursor[NN];
__device__ int2  g_edge[NNZ_E];   // {col, bitcast(val)} sorted by row

#define SCAN_B 1024
#define NSCAN ((NN + SCAN_B - 1) / SCAN_B)   // 98 blocks
__device__ int g_part[NSCAN];

__global__ void k_zero() {
    int i = blockIdx.x * blockDim.x + threadIdx.x;
    if (i < NN) g_count[i] = 0;
}

__global__ void k_hist(const int* __restrict__ rows) {
    int e = blockIdx.x * blockDim.x + threadIdx.x;
    if (e < NNZ_E) atomicAdd(&g_count[rows[e]], 1);
}

// block sums of 1024-element chunks
__global__ void k_scanA() {
    __shared__ int sh[256];
    int base = blockIdx.x * SCAN_B;
    int s = 0;
    for (int j = threadIdx.x; j < SCAN_B; j += 256) {
        int idx = base + j;
        if (idx < NN) s += g_count[idx];
    }
    sh[threadIdx.x] = s;
    __syncthreads();
    for (int off = 128; off > 0; off >>= 1) {
        if (threadIdx.x < off) sh[threadIdx.x] += sh[threadIdx.x + off];
        __syncthreads();
    }
    if (threadIdx.x == 0) g_part[blockIdx.x] = sh[0];
}

// exclusive scan of 98 partials (trivial serial)
__global__ void k_scanB() {
    if (threadIdx.x == 0) {
        int a = 0;
        for (int b = 0; b < NSCAN; b++) { int t = g_part[b]; g_part[b] = a; a += t; }
    }
}

// per-chunk exclusive scan + partial offset -> row_start, row_cursor
__global__ void k_scanC() {
    __shared__ int sh[SCAN_B];
    int i = blockIdx.x * SCAN_B + threadIdx.x;
    int v = (i < NN) ? g_count[i] : 0;
    sh[threadIdx.x] = v;
    __syncthreads();
    for (int off = 1; off < SCAN_B; off <<= 1) {
        int t = (threadIdx.x >= (unsigned)off) ? sh[threadIdx.x - off] : 0;
        __syncthreads();
        sh[threadIdx.x] += t;
        __syncthreads();
    }
    if (i < NN) {
        int excl = sh[threadIdx.x] - v + g_part[blockIdx.x];
        g_start[i]  = excl;
        g_cursor[i] = excl;
    }
}

__global__ void k_scatter(const float* __restrict__ vals,
                          const int* __restrict__ rows,
                          const int* __restrict__ cols) {
    int e = blockIdx.x * blockDim.x + threadIdx.x;
    if (e >= NNZ_E) return;
    int r = rows[e];
    int p = atomicAdd(&g_cursor[r], 1);
    g_edge[p] = make_int2(cols[e], __float_as_int(vals[e]));
}

// One warp per row. Lane layout: half = lane>>4 (edge parity),
// seg = lane&15 (float4 chunk of the 64-wide embedding row).
// Gather source is split across two base pointers (layer 1: u / it;
// layers 2-3: same pointer with split=NN so the first branch always wins).
__global__ void __launch_bounds__(256) k_spmm(const float4* __restrict__ xu,
                                              const float4* __restrict__ xi,
                                              int split,
                                              float4* __restrict__ y) {
    int w    = (blockIdx.x * blockDim.x + threadIdx.x) >> 5;
    int lane = threadIdx.x & 31;
    if (w >= NN) return;
    int half = lane >> 4;
    int seg  = lane & 15;

    int s = g_start[w];
    int n = g_count[w];
    float4 a = make_float4(0.f, 0.f, 0.f, 0.f);

    int j = 0;
    for (; j + 4 <= n; j += 4) {                 // 4 edges per iter, 2 per half
        int2 e0 = g_edge[s + j + half];
        int2 e1 = g_edge[s + j + 2 + half];
        const float4* b0 = (e0.x < split) ? (xu + (size_t)e0.x * 16)
                                          : (xi + (size_t)(e0.x - split) * 16);
        const float4* b1 = (e1.x < split) ? (xu + (size_t)e1.x * 16)
                                          : (xi + (size_t)(e1.x - split) * 16);
        float4 x0 = b0[seg];
        float4 x1 = b1[seg];
        float v0 = __int_as_float(e0.y);
        float v1 = __int_as_float(e1.y);
        a.x = fmaf(v0, x0.x, a.x); a.y = fmaf(v0, x0.y, a.y);
        a.z = fmaf(v0, x0.z, a.z); a.w = fmaf(v0, x0.w, a.w);
        a.x = fmaf(v1, x1.x, a.x); a.y = fmaf(v1, x1.y, a.y);
        a.z = fmaf(v1, x1.z, a.z); a.w = fmaf(v1, x1.w, a.w);
    }
    for (; j < n; j += 2) {                      // tail: up to 2 edges
        int idx = j + half;
        int2 e = (idx < n) ? g_edge[s + idx] : make_int2(0, 0);
        const float4* b = (e.x < split) ? (xu + (size_t)e.x * 16)
                                        : (xi + (size_t)(e.x - split) * 16);
        float4 x = b[seg];
        float v = __int_as_float(e.y);
        a.x = fmaf(v, x.x, a.x); a.y = fmaf(v, x.y, a.y);
        a.z = fmaf(v, x.z, a.z); a.w = fmaf(v, x.w, a.w);
    }

    // combine the two edge-parity halves
    a.x += __shfl_xor_sync(0xffffffffu, a.x, 16);
    a.y += __shfl_xor_sync(0xffffffffu, a.y, 16);
    a.z += __shfl_xor_sync(0xffffffffu, a.z, 16);
    a.w += __shfl_xor_sync(0xffffffffu, a.w, 16);

    if (half == 0) y[(size_t)w * 16 + seg] = a;
}

// out = 0.25 * (ego0 + l1 + l2 + l3); ego0 read straight from inputs
__global__ void k_comb(const float4* __restrict__ u,
                       const float4* __restrict__ it,
                       float4* __restrict__ out) {
    int i = blockIdx.x * blockDim.x + threadIdx.x;
    const int nU = N_USERS * EMB / 4;
    const int nT = NV / 4;
    if (i >= nT) return;
    float4 e = (i < nU) ? u[i] : it[i - nU];
    float4 a = ((const float4*)g_buf0)[i];
    float4 b = ((const float4*)g_buf1)[i];
    float4 c = ((const float4*)g_buf2)[i];
    float4 o;
    o.x = 0.25f * (e.x + a.x + b.x + c.x);
    o.y = 0.25f * (e.y + a.y + b.y + c.y);
    o.z = 0.25f * (e.z + a.z + b.z + c.z);
    o.w = 0.25f * (e.w + a.w + b.w + c.w);
    out[i] = o;
}

extern "C" void kernel_launch(void* const* d_in, const int* in_sizes, int n_in,
                              void* d_out, int out_size) {
    const float4* u    = (const float4*)d_in[0];   // user_emb  [60000,64] f32
    const float4* it   = (const float4*)d_in[1];   // item_emb  [40000,64] f32
    const float*  vals = (const float*) d_in[2];   // adj_vals  [2M] f32
    const int*    rows = (const int*)   d_in[3];   // adj_rows  [2M] i32
    const int*    cols = (const int*)   d_in[4];   // adj_cols  [2M] i32
    float* out = (float*)d_out;                    // [100000, 64] f32

    k_zero<<<(NN + 255) / 256, 256>>>();
    k_hist<<<(NNZ_E + 255) / 256, 256>>>(rows);
    k_scanA<<<NSCAN, 256>>>();
    k_scanB<<<1, 32>>>();
    k_scanC<<<NSCAN, SCAN_B>>>();
    k_scatter<<<(NNZ_E + 255) / 256, 256>>>(vals, rows, cols);

    const int spmm_blocks = (NN * 32 + 255) / 256;   // one warp per row
    float4* b0 = nullptr; float4* b1 = nullptr; float4* b2 = nullptr;
    cudaGetSymbolAddress((void**)&b0, g_buf0);
    cudaGetSymbolAddress((void**)&b1, g_buf1);
    cudaGetSymbolAddress((void**)&b2, g_buf2);

    k_spmm<<<spmm_blocks, 256>>>(u, it, N_USERS, b0);          // layer 1
    k_spmm<<<spmm_blocks, 256>>>(b0, b0, NN, b1);              // layer 2
    k_spmm<<<spmm_blocks, 256>>>(b1, b1, NN, b2);              // layer 3

    k_comb<<<(NV / 4 + 255) / 256, 256>>>(u, it, (float4*)out);
}

// round 5
// speedup vs baseline: 1.5038x; 1.0760x over previous
#include <cuda_runtime.h>
#include <cuda_fp16.h>

// LightGCN: counting-sort COO->CSR, then 3 warp-per-row gather SpMM layers.
// Gather operands stored fp16 (halves L2 gather traffic); accumulate f32.
// Layer-3 output kept f32 (never gathered). out = 0.25*(ego_f32+l1+l2+l3).

#define N_USERS 60000
#define N_ITEMS 40000
#define NN      100000
#define NNZ_E   2000000
#define EMB     64
#define NV      (NN * EMB)      // 6.4M floats

// ---- scratch (device globals) ----
__device__ uint4 g_h0[NV / 8];    // ego, fp16      (12.8 MB)
__device__ uint4 g_h1[NV / 8];    // layer-1, fp16
__device__ uint4 g_h2[NV / 8];    // layer-2, fp16
__device__ float g_f3[NV];        // layer-3, f32   (25.6 MB)
__device__ int   g_count[NN];
__device__ int   g_start[NN];
__device__ int   g_cursor[NN];
__device__ int2  g_edge[NNZ_E];   // {col, bitcast(val)} sorted by row

#define SCAN_B 1024
#define NSCAN ((NN + SCAN_B - 1) / SCAN_B)   // 98
__device__ int g_part[NSCAN];

// ---- fp16 bitcast helpers ----
__device__ __forceinline__ unsigned h2_as_u(__half2 h) {
    return *reinterpret_cast<unsigned*>(&h);
}
__device__ __forceinline__ __half2 u_as_h2(unsigned u) {
    return *reinterpret_cast<__half2*>(&u);
}
__device__ __forceinline__ uint2 pack_h4(float4 v) {
    return make_uint2(h2_as_u(__floats2half2_rn(v.x, v.y)),
                      h2_as_u(__floats2half2_rn(v.z, v.w)));
}
__device__ __forceinline__ void fma_h4(float4& a, float v, uint2 p) {
    float2 lo = __half22float2(u_as_h2(p.x));
    float2 hi = __half22float2(u_as_h2(p.y));
    a.x = fmaf(v, lo.x, a.x); a.y = fmaf(v, lo.y, a.y);
    a.z = fmaf(v, hi.x, a.z); a.w = fmaf(v, hi.y, a.w);
}

__global__ void k_zero() {
    int i = blockIdx.x * blockDim.x + threadIdx.x;
    if (i < NN) g_count[i] = 0;
}

// convert concat(u,it) f32 -> fp16 into g_h0
__global__ void k_conv(const float4* __restrict__ u,
                       const float4* __restrict__ it) {
    int i = blockIdx.x * blockDim.x + threadIdx.x;
    const int nU = N_USERS * EMB / 4;
    const int nT = NV / 4;
    if (i >= nT) return;
    float4 v = (i < nU) ? u[i] : it[i - nU];
    ((uint2*)g_h0)[i] = pack_h4(v);
}

__global__ void k_hist(const int* __restrict__ rows) {
    int e = blockIdx.x * blockDim.x + threadIdx.x;
    if (e < NNZ_E) atomicAdd(&g_count[rows[e]], 1);
}

__global__ void k_scanA() {
    __shared__ int sh[256];
    int base = blockIdx.x * SCAN_B;
    int s = 0;
    for (int j = threadIdx.x; j < SCAN_B; j += 256) {
        int idx = base + j;
        if (idx < NN) s += g_count[idx];
    }
    sh[threadIdx.x] = s;
    __syncthreads();
    for (int off = 128; off > 0; off >>= 1) {
        if (threadIdx.x < off) sh[threadIdx.x] += sh[threadIdx.x + off];
        __syncthreads();
    }
    if (threadIdx.x == 0) g_part[blockIdx.x] = sh[0];
}

// exclusive scan of 98 partials, parallel (128 threads, Hillis-Steele)
__global__ void k_scanB() {
    __shared__ int sh[128];
    int t = threadIdx.x;
    int v = (t < NSCAN) ? g_part[t] : 0;
    sh[t] = v;
    __syncthreads();
    for (int off = 1; off < 128; off <<= 1) {
        int x = (t >= off) ? sh[t - off] : 0;
        __syncthreads();
        sh[t] += x;
        __syncthreads();
    }
    if (t < NSCAN) g_part[t] = sh[t] - v;   // exclusive
}

__global__ void k_scanC() {
    __shared__ int sh[SCAN_B];
    int i = blockIdx.x * SCAN_B + threadIdx.x;
    int v = (i < NN) ? g_count[i] : 0;
    sh[threadIdx.x] = v;
    __syncthreads();
    for (int off = 1; off < SCAN_B; off <<= 1) {
        int t = (threadIdx.x >= (unsigned)off) ? sh[threadIdx.x - off] : 0;
        __syncthreads();
        sh[threadIdx.x] += t;
        __syncthreads();
    }
    if (i < NN) {
        int excl = sh[threadIdx.x] - v + g_part[blockIdx.x];
        g_start[i]  = excl;
        g_cursor[i] = excl;
    }
}

__global__ void k_scatter(const float* __restrict__ vals,
                          const int* __restrict__ rows,
                          const int* __restrict__ cols) {
    int e = blockIdx.x * blockDim.x + threadIdx.x;
    if (e >= NNZ_E) return;
    int r = rows[e];
    int p = atomicAdd(&g_cursor[r], 1);
    g_edge[p] = make_int2(cols[e], __float_as_int(vals[e]));
}

// One warp per row. half = lane>>4 (edge parity), seg = lane&15 owns
// 4 consecutive halves (8 B) of the 64-wide fp16 row (16*8B = 128B/row).
// OUT_F32: write float4 row (layer 3) else pack to fp16.
template <bool OUT_F32>
__global__ void __launch_bounds__(256) k_spmm(const uint2* __restrict__ x,
                                              void* __restrict__ y) {
    int w    = (blockIdx.x * blockDim.x + threadIdx.x) >> 5;
    int lane = threadIdx.x & 31;
    if (w >= NN) return;
    int half = lane >> 4;
    int seg  = lane & 15;

    int s = g_start[w];
    int n = g_count[w];
    float4 a = make_float4(0.f, 0.f, 0.f, 0.f);

    int j = 0;
    for (; j + 4 <= n; j += 4) {
        int2 e0 = g_edge[s + j + half];
        int2 e1 = g_edge[s + j + 2 + half];
        uint2 x0 = x[(size_t)e0.x * 16 + seg];
        uint2 x1 = x[(size_t)e1.x * 16 + seg];
        fma_h4(a, __int_as_float(e0.y), x0);
        fma_h4(a, __int_as_float(e1.y), x1);
    }
    for (; j < n; j += 2) {
        int idx = j + half;
        bool ok = idx < n;
        int2 e = ok ? g_edge[s + idx] : make_int2(0, 0);
        int col = ok ? e.x : 0;
        uint2 xv = x[(size_t)col * 16 + seg];
        float v = ok ? __int_as_float(e.y) : 0.f;
        fma_h4(a, v, xv);
    }

    a.x += __shfl_xor_sync(0xffffffffu, a.x, 16);
    a.y += __shfl_xor_sync(0xffffffffu, a.y, 16);
    a.z += __shfl_xor_sync(0xffffffffu, a.z, 16);
    a.w += __shfl_xor_sync(0xffffffffu, a.w, 16);

    if (half == 0) {
        if (OUT_F32) {
            ((float4*)y)[(size_t)w * 16 + seg] = a;
        } else {
            ((uint2*)y)[(size_t)w * 16 + seg] = pack_h4(a);
        }
    }
}

// out = 0.25 * (ego_f32 + l1_h + l2_h + l3_f32)
__global__ void k_comb(const float4* __restrict__ u,
                       const float4* __restrict__ it,
                       float4* __restrict__ out) {
    int i = blockIdx.x * blockDim.x + threadIdx.x;
    const int nU = N_USERS * EMB / 4;
    const int nT = NV / 4;
    if (i >= nT) return;
    float4 e = (i < nU) ? u[i] : it[i - nU];
    float4 c = ((const float4*)g_f3)[i];
    float4 a = make_float4(e.x + c.x, e.y + c.y, e.z + c.z, e.w + c.w);
    fma_h4(a, 1.f, ((const uint2*)g_h1)[i]);
    fma_h4(a, 1.f, ((const uint2*)g_h2)[i]);
    out[i] = make_float4(0.25f * a.x, 0.25f * a.y, 0.25f * a.z, 0.25f * a.w);
}

extern "C" void kernel_launch(void* const* d_in, const int* in_sizes, int n_in,
                              void* d_out, int out_size) {
    const float4* u    = (const float4*)d_in[0];
    const float4* it   = (const float4*)d_in[1];
    const float*  vals = (const float*) d_in[2];
    const int*    rows = (const int*)   d_in[3];
    const int*    cols = (const int*)   d_in[4];
    float* out = (float*)d_out;

    k_zero<<<(NN + 255) / 256, 256>>>();
    k_conv<<<(NV / 4 + 255) / 256, 256>>>(u, it);
    k_hist<<<(NNZ_E + 255) / 256, 256>>>(rows);
    k_scanA<<<NSCAN, 256>>>();
    k_scanB<<<1, 128>>>();
    k_scanC<<<NSCAN, SCAN_B>>>();
    k_scatter<<<(NNZ_E + 255) / 256, 256>>>(vals, rows, cols);

    uint2* h0; uint2* h1; uint2* h2; float* f3;
    cudaGetSymbolAddress((void**)&h0, g_h0);
    cudaGetSymbolAddress((void**)&h1, g_h1);
    cudaGetSymbolAddress((void**)&h2, g_h2);
    cudaGetSymbolAddress((void**)&f3, g_f3);

    const int spmm_blocks = (NN * 32 + 255) / 256;
    k_spmm<false><<<spmm_blocks, 256>>>(h0, h1);   // layer 1 (fp16 out)
    k_spmm<false><<<spmm_blocks, 256>>>(h1, h2);   // layer 2 (fp16 out)
    k_spmm<true ><<<spmm_blocks, 256>>>(h2, f3);   // layer 3 (f32 out)

    k_comb<<<(NV / 4 + 255) / 256, 256>>>(u, it, (float4*)out);
}